// round 15
// baseline (speedup 1.0000x reference)
#include <cuda_runtime.h>
#include <cstdint>

// CostVolume: out[b,d,h,x] = (1/128) * sum_c L[b,c,h,x]*R[b,c,h,x-d], x>=d else 0
// B=8 C=128 H=128 W=240 V=48
// Warp-specialized R11: 4 compute warps (XT=4, IT=24, parity-phased pairing,
// 2-stage operand double-buffering) + 1 producer warp issuing all cp.async.
// Handoff via mbarrier pairs: full <- cp.async.mbarrier.arrive.NOINC (count
// 32), empty <- consumer arrives (count 128). No __syncthreads in main loop.
#define B_  8
#define C_  128
#define H_  128
#define W_  240
#define V_  48
#define HW_ (H_*W_)

#define CC   16            // channels per chunk
#define NCH  (C_/CC)       // 8 chunks
#define THREADS 160        // 128 compute + 32 producer
#define RW   288           // sR row width: 48 zero pad + 240 data

// smem float layout: sL [2][CC][W_], sR [2][CC][RW], then 4 mbarriers.
#define SL_FLOATS (2*CC*W_)
#define SR_FLOATS (2*CC*RW)
#define MB_OFF    ((SL_FLOATS + SR_FLOATS) * 4)     // byte offset of mbarriers
#define SMEM_BYTES (MB_OFF + 64)

typedef unsigned long long ull;

__device__ __forceinline__ ull pk(float lo, float hi) {
    ull r; asm("mov.b64 %0, {%1, %2};" : "=l"(r) : "f"(lo), "f"(hi)); return r;
}
__device__ __forceinline__ void upk(ull v, float& lo, float& hi) {
    asm("mov.b64 {%0, %1}, %2;" : "=f"(lo), "=f"(hi) : "l"(v));
}
__device__ __forceinline__ void fma2(ull& acc, ull a, ull b) {
    asm("fma.rn.f32x2 %0, %1, %2, %0;" : "+l"(acc) : "l"(a), "l"(b));
}
__device__ __forceinline__ void cpasync16(uint32_t saddr, const void* g) {
    asm volatile("cp.async.cg.shared.global [%0], [%1], 16;" :: "r"(saddr), "l"(g));
}
__device__ __forceinline__ void mbar_init(uint32_t a, uint32_t cnt) {
    asm volatile("mbarrier.init.shared.b64 [%0], %1;" :: "r"(a), "r"(cnt) : "memory");
}
__device__ __forceinline__ void mbar_arrive(uint32_t a) {
    asm volatile("mbarrier.arrive.shared.b64 _, [%0];" :: "r"(a) : "memory");
}
__device__ __forceinline__ void mbar_wait(uint32_t a, uint32_t parity) {
    asm volatile(
        "{ .reg .pred P;\n\t"
        "W%=:\n\t"
        "mbarrier.try_wait.parity.acquire.cta.shared::cta.b64 P, [%0], %1, 0x989680;\n\t"
        "@P bra.uni D%=;\n\t"
        "bra.uni W%=;\n\t"
        "D%=:\n\t }"
        :: "r"(a), "r"(parity) : "memory");
}

struct Stage {
    float4 Lq; float Ls;
    float2 r0;
    float4 r1, r2, r3, r4, r5, r6;
};

__global__ void __launch_bounds__(THREADS, 2)
cv_kernel(const float* __restrict__ L, const float* __restrict__ R,
          float* __restrict__ out)
{
    extern __shared__ float smem[];
    float* sL = smem;                       // [2][CC][W_]
    float* sR = smem + SL_FLOATS;           // [2][CC][RW]
    const uint32_t smb = (uint32_t)__cvta_generic_to_shared(smem);
    const uint32_t mbFull0  = smb + MB_OFF;
    const uint32_t mbFull1  = smb + MB_OFF + 8;
    const uint32_t mbEmpty0 = smb + MB_OFF + 16;
    const uint32_t mbEmpty1 = smb + MB_OFF + 24;

    const int tid = threadIdx.x;
    const int h = blockIdx.x;
    const int b = blockIdx.y;

    const float* Lbase = L + ((size_t)b * C_ * H_ + h) * W_;
    const float* Rbase = R + ((size_t)b * C_ * H_ + h) * W_;

    if (tid == 0) {
        mbar_init(mbFull0, 32);  mbar_init(mbFull1, 32);
        mbar_init(mbEmpty0, 128); mbar_init(mbEmpty1, 128);
    }
    // Zero the left pad of sR (x<0 -> 0), both buffers, once (all threads).
    for (int idx = tid; idx < 2 * CC * 48; idx += THREADS) {
        int buf = idx / (CC * 48);
        int rem = idx - buf * (CC * 48);
        int r = rem / 48, k = rem - r * 48;
        sR[buf * (CC * RW) + r * RW + k] = 0.0f;
    }
    __syncthreads();   // mbarriers + pads visible; only sync in the kernel

    if (tid >= 128) {
        // ---------------- producer warp ----------------
        const int pt = tid - 128;             // 0..31
        const int prow = pt >> 1;              // chunk-local row 0..15
        const int pc0  = (pt & 1) * 30;        // quad col base 0 or 30
        const float* gLp = Lbase + (size_t)prow * HW_ + pc0 * 4;
        const float* gRp = Rbase + (size_t)prow * HW_ + pc0 * 4;
        const uint32_t sLp = smb + (uint32_t)(prow * W_ + pc0 * 4) * 4;
        const uint32_t sRp = smb + (uint32_t)(SL_FLOATS + prow * RW + 48 + pc0 * 4) * 4;

        int ep0 = 0, ep1 = 0;
        #pragma unroll 1
        for (int ch = 0; ch < NCH; ch++) {
            const int buf = ch & 1;
            if (ch >= 2) {
                if (buf == 0) { mbar_wait(mbEmpty0, ep0); ep0 ^= 1; }
                else          { mbar_wait(mbEmpty1, ep1); ep1 ^= 1; }
            }
            const uint32_t dL = sLp + (uint32_t)buf * (CC * W_ * 4);
            const uint32_t dR = sRp + (uint32_t)buf * (CC * RW * 4);
            #pragma unroll
            for (int k = 0; k < 30; k++)
                cpasync16(dL + k * 16, gLp + k * 4);
            #pragma unroll
            for (int k = 0; k < 30; k++)
                cpasync16(dR + k * 16, gRp + k * 4);
            // NOINC: completion of this thread's prior cp.asyncs performs ONE
            // arrival (init count 32 = producer warp size).
            asm volatile("cp.async.mbarrier.arrive.noinc.shared.b64 [%0];"
                         :: "r"(buf ? mbFull1 : mbFull0) : "memory");
            gLp += CC * HW_; gRp += CC * HW_;
        }
        return;
    }

    // ---------------- compute warps (tid < 128): R11 math ----------------
    const int xg = tid & 63;          // 0..63 (60 active)
    const int ig = tid >> 6;          // 0..1
    const int i0 = ig * 24;           // disparity base
    const int xb = xg * 4;
    const bool act  = (xg < 60);
    const bool edge = (xg < 59);

    ull accE[12][2], accO[12][2];
    #pragma unroll
    for (int j = 0; j < 12; j++) {
        accE[j][0] = 0ull; accE[j][1] = 0ull;
        accO[j][0] = 0ull; accO[j][1] = 0ull;
    }

    int fp0 = 0, fp1 = 0;
    #pragma unroll 1
    for (int ch = 0; ch < NCH; ch++) {
        const int buf = ch & 1;
        if (buf == 0) { mbar_wait(mbFull0, fp0); fp0 ^= 1; }
        else          { mbar_wait(mbFull1, fp1); fp1 ^= 1; }

        if (act) {
            const float* lw = &sL[buf * (CC * W_)] + xb;
            const float* rw = &sR[buf * (CC * RW)] + (xb - i0 + 24);
            Stage SA, SB;

            #define LDS_STAGE(S, cc) do {                                   \
                (S).Lq = *(const float4*)(lw + (cc) * W_);                  \
                (S).Ls = lw[(cc) * W_ + 4];                                 \
                (S).r0 = *(const float2*)(rw + (cc) * RW + 2);              \
                (S).r1 = *(const float4*)(rw + (cc) * RW + 4);              \
                (S).r2 = *(const float4*)(rw + (cc) * RW + 8);              \
                (S).r3 = *(const float4*)(rw + (cc) * RW + 12);             \
                (S).r4 = *(const float4*)(rw + (cc) * RW + 16);             \
                (S).r5 = *(const float4*)(rw + (cc) * RW + 20);             \
                (S).r6 = *(const float4*)(rw + (cc) * RW + 24);             \
            } while (0)

            #define FMA_STAGE(S) do {                                       \
                ull Le0 = pk((S).Lq.x, (S).Lq.y);                           \
                ull Le1 = pk((S).Lq.z, (S).Lq.w);                           \
                ull Lo0 = pk((S).Lq.y, (S).Lq.z);                           \
                ull Lo1 = pk((S).Lq.w, (S).Ls);                             \
                ull P[14];                                                  \
                P[1]  = pk((S).r0.x, (S).r0.y);                             \
                P[2]  = pk((S).r1.x, (S).r1.y); P[3]  = pk((S).r1.z, (S).r1.w); \
                P[4]  = pk((S).r2.x, (S).r2.y); P[5]  = pk((S).r2.z, (S).r2.w); \
                P[6]  = pk((S).r3.x, (S).r3.y); P[7]  = pk((S).r3.z, (S).r3.w); \
                P[8]  = pk((S).r4.x, (S).r4.y); P[9]  = pk((S).r4.z, (S).r4.w); \
                P[10] = pk((S).r5.x, (S).r5.y); P[11] = pk((S).r5.z, (S).r5.w); \
                P[12] = pk((S).r6.x, (S).r6.y); P[13] = pk((S).r6.z, (S).r6.w); \
                _Pragma("unroll")                                           \
                for (int j = 0; j < 12; j++) {                              \
                    fma2(accE[j][0], Le0, P[12 - j]);                       \
                    fma2(accO[j][0], Lo0, P[12 - j]);                       \
                    fma2(accE[j][1], Le1, P[13 - j]);                       \
                    fma2(accO[j][1], Lo1, P[13 - j]);                       \
                }                                                           \
            } while (0)

            LDS_STAGE(SA, 0);
            #pragma unroll
            for (int cc = 0; cc < CC; cc += 2) {
                if (cc + 1 < CC) LDS_STAGE(SB, cc + 1);
                FMA_STAGE(SA);
                if (cc + 2 < CC) LDS_STAGE(SA, cc + 2);
                if (cc + 1 < CC) FMA_STAGE(SB);
            }
            #undef LDS_STAGE
            #undef FMA_STAGE
        }
        mbar_arrive(buf ? mbEmpty1 : mbEmpty0);
    }

    const float s = 1.0f / 128.0f;
    if (act) {
        #pragma unroll
        for (int j = 0; j < 12; j++) {
            const int de = i0 + 2 * j;
            float a0, a1, a2, a3;
            upk(accE[j][0], a0, a1);
            upk(accE[j][1], a2, a3);
            float4 o;
            o.x = a0 * s; o.y = a1 * s; o.z = a2 * s; o.w = a3 * s;
            *(float4*)(out + (((size_t)b * V_ + de) * H_ + h) * W_ + xb) = o;

            float b0, b1, b2, b3;
            upk(accO[j][0], b0, b1);
            upk(accO[j][1], b2, b3);
            float* oo = out + (((size_t)b * V_ + de + 1) * H_ + h) * W_ + xb;
            oo[1] = b0 * s;
            oo[2] = b1 * s;
            oo[3] = b2 * s;
            if (edge) oo[4] = b3 * s;     // x=xb+4; xg=59 skips x=240
        }
    } else if (xg == 60) {
        // out[x=0, odd d]: never produced by the odd pipeline; 0 since x<d.
        #pragma unroll
        for (int j = 0; j < 12; j++) {
            const int d = i0 + 2 * j + 1;
            out[(((size_t)b * V_ + d) * H_ + h) * W_] = 0.0f;
        }
    }
}

extern "C" void kernel_launch(void* const* d_in, const int* in_sizes, int n_in,
                              void* d_out, int out_size)
{
    const float* L = (const float*)d_in[0];
    const float* R = (const float*)d_in[1];
    float* out = (float*)d_out;

    cudaFuncSetAttribute(cv_kernel, cudaFuncAttributeMaxDynamicSharedMemorySize,
                         SMEM_BYTES);
    cv_kernel<<<dim3(H_, B_), THREADS, SMEM_BYTES>>>(L, R, out);
}

// round 16
// speedup vs baseline: 1.4068x; 1.4068x over previous
#include <cuda_runtime.h>
#include <cstdint>

// CostVolume: out[b,d,h,x] = (1/128) * sum_c L[b,c,h,x]*R[b,c,h,x-d], x>=d else 0
// B=8 C=128 H=128 W=240 V=48
// R11 platform (XT=4, IT=24, parity-phased pairing, 2-stage operand
// double-buffering, division-free loader) with the conflicted 4-cyc L-scalar
// LDS replaced by a 1-cyc __shfl_down from lane+1, and an unguarded main loop
// (inactive lanes compute discarded garbage; smem padded for their reads).
#define B_  8
#define C_  128
#define H_  128
#define W_  240
#define V_  48
#define HW_ (H_*W_)

#define CC   16            // channels per chunk
#define NCH  (C_/CC)       // 8 chunks
#define THREADS 128
#define RW   288           // sR row width: 48 zero pad + 240 data

typedef unsigned long long ull;

__device__ __forceinline__ ull pk(float lo, float hi) {
    ull r; asm("mov.b64 %0, {%1, %2};" : "=l"(r) : "f"(lo), "f"(hi)); return r;
}
__device__ __forceinline__ void upk(ull v, float& lo, float& hi) {
    asm("mov.b64 {%0, %1}, %2;" : "=f"(lo), "=f"(hi) : "l"(v));
}
__device__ __forceinline__ void fma2(ull& acc, ull a, ull b) {
    asm("fma.rn.f32x2 %0, %1, %2, %0;" : "+l"(acc) : "l"(a), "l"(b));
}
__device__ __forceinline__ void cpasync16(uint32_t saddr, const void* g) {
    asm volatile("cp.async.cg.shared.global [%0], [%1], 16;" :: "r"(saddr), "l"(g));
}

struct Stage {
    float4 Lq;
    float2 r0;
    float4 r1, r2, r3, r4, r5, r6;
};

__global__ void __launch_bounds__(THREADS, 3)
cv_kernel(const float* __restrict__ L, const float* __restrict__ R,
          float* __restrict__ out)
{
    extern __shared__ float smem[];
    float* sL = smem;                 // [2][CC][W_]
    float* sR = smem + 2 * CC * W_;   // [2][CC][RW]  (+16-float tail pad)

    const int tid  = threadIdx.x;
    const int lane = tid & 31;
    const int h = blockIdx.x;
    const int b = blockIdx.y;

    const int xg = tid & 63;          // 0..63 (60 active)
    const int ig = tid >> 6;          // 0..1
    const int i0 = ig * 24;           // disparity base
    const int xb = xg * 4;
    const bool act  = (xg < 60);
    const bool edge = (xg < 59);

    const float* Lbase = L + ((size_t)b * C_ * H_ + h) * W_;
    const float* Rbase = R + ((size_t)b * C_ * H_ + h) * W_;

    // Zero the left pad of sR (x<0 -> 0), both buffers, once.
    for (int idx = tid; idx < 2 * CC * 48; idx += THREADS) {
        int buf = idx / (CC * 48);
        int rem = idx - buf * (CC * 48);
        int r = rem / 48, k = rem - r * 48;
        sR[buf * (CC * RW) + r * RW + k] = 0.0f;
    }

    // --- division-free loader: thread<120 owns (row0, col); rows row0+2k ---
    const bool loader = (tid < 120);
    const int lr0  = (tid >= 60) ? 1 : 0;
    const int lcol = tid - lr0 * 60;             // 0..59 (quad index)
    const float* gL = Lbase + (size_t)lr0 * HW_ + lcol * 4;
    const float* gR = Rbase + (size_t)lr0 * HW_ + lcol * 4;
    const uint32_t sLb = (uint32_t)__cvta_generic_to_shared(sL)
                       + (uint32_t)(lr0 * W_ + lcol * 4) * 4;
    const uint32_t sRb = (uint32_t)__cvta_generic_to_shared(sR)
                       + (uint32_t)(lr0 * RW + 48 + lcol * 4) * 4;

    auto issue_load = [&](int buf) {
        if (loader) {
            const uint32_t dL = sLb + (uint32_t)buf * (CC * W_ * 4);
            const uint32_t dR = sRb + (uint32_t)buf * (CC * RW * 4);
            #pragma unroll
            for (int k = 0; k < 8; k++) {        // rows lr0 + 2k
                cpasync16(dL + k * (2 * W_ * 4), gL + (size_t)k * 2 * HW_);
                cpasync16(dR + k * (2 * RW * 4), gR + (size_t)k * 2 * HW_);
            }
        }
        asm volatile("cp.async.commit_group;");
    };

    // accE[j]: d=i0+2j,  x pairs (xb,xb+1),(xb+2,xb+3)
    // accO[j]: d=i0+2j+1, x pairs (xb+1,xb+2),(xb+3,xb+4)
    ull accE[12][2], accO[12][2];
    #pragma unroll
    for (int j = 0; j < 12; j++) {
        accE[j][0] = 0ull; accE[j][1] = 0ull;
        accO[j][0] = 0ull; accO[j][1] = 0ull;
    }

    issue_load(0);
    gL += CC * HW_; gR += CC * HW_;

    #pragma unroll 1
    for (int ch = 0; ch < NCH; ch++) {
        const int buf = ch & 1;
        if (ch + 1 < NCH) {
            issue_load((ch + 1) & 1);
            gL += CC * HW_; gR += CC * HW_;
            asm volatile("cp.async.wait_group 1;");
        } else {
            asm volatile("cp.async.wait_group 0;");
        }
        __syncthreads();

        {   // UNGUARDED main loop: xg>=60 lanes compute garbage, never stored.
            const float* lw = &sL[buf * (CC * W_)] + xb;
            const float* rw = &sR[buf * (CC * RW)] + (xb - i0 + 24);
            Stage SA, SB;

            #define LDS_STAGE(S, cc) do {                                   \
                (S).Lq = *(const float4*)(lw + (cc) * W_);                  \
                (S).r0 = *(const float2*)(rw + (cc) * RW + 2);              \
                (S).r1 = *(const float4*)(rw + (cc) * RW + 4);              \
                (S).r2 = *(const float4*)(rw + (cc) * RW + 8);              \
                (S).r3 = *(const float4*)(rw + (cc) * RW + 12);             \
                (S).r4 = *(const float4*)(rw + (cc) * RW + 16);             \
                (S).r5 = *(const float4*)(rw + (cc) * RW + 20);             \
                (S).r6 = *(const float4*)(rw + (cc) * RW + 24);             \
            } while (0)

            // Ls = L[xb+4] = lane+1's Lq.x (16B lane stride); lane 31 needs
            // the cross-warp value -> 1-lane patch load.
            #define FMA_STAGE(S, cc) do {                                   \
                float Lsv = __shfl_down_sync(0xffffffffu, (S).Lq.x, 1);     \
                if (lane == 31) Lsv = lw[(cc) * W_ + 4];                    \
                ull Le0 = pk((S).Lq.x, (S).Lq.y);                           \
                ull Le1 = pk((S).Lq.z, (S).Lq.w);                           \
                ull Lo0 = pk((S).Lq.y, (S).Lq.z);                           \
                ull Lo1 = pk((S).Lq.w, Lsv);                                \
                ull P[14];                                                  \
                P[1]  = pk((S).r0.x, (S).r0.y);                             \
                P[2]  = pk((S).r1.x, (S).r1.y); P[3]  = pk((S).r1.z, (S).r1.w); \
                P[4]  = pk((S).r2.x, (S).r2.y); P[5]  = pk((S).r2.z, (S).r2.w); \
                P[6]  = pk((S).r3.x, (S).r3.y); P[7]  = pk((S).r3.z, (S).r3.w); \
                P[8]  = pk((S).r4.x, (S).r4.y); P[9]  = pk((S).r4.z, (S).r4.w); \
                P[10] = pk((S).r5.x, (S).r5.y); P[11] = pk((S).r5.z, (S).r5.w); \
                P[12] = pk((S).r6.x, (S).r6.y); P[13] = pk((S).r6.z, (S).r6.w); \
                _Pragma("unroll")                                           \
                for (int j = 0; j < 12; j++) {                              \
                    fma2(accE[j][0], Le0, P[12 - j]);                       \
                    fma2(accO[j][0], Lo0, P[12 - j]);                       \
                    fma2(accE[j][1], Le1, P[13 - j]);                       \
                    fma2(accO[j][1], Lo1, P[13 - j]);                       \
                }                                                           \
            } while (0)

            LDS_STAGE(SA, 0);
            #pragma unroll
            for (int cc = 0; cc < CC; cc += 2) {
                if (cc + 1 < CC) LDS_STAGE(SB, cc + 1);
                FMA_STAGE(SA, cc);
                if (cc + 2 < CC) LDS_STAGE(SA, cc + 2);
                if (cc + 1 < CC) FMA_STAGE(SB, cc + 1);
            }
            #undef LDS_STAGE
            #undef FMA_STAGE
        }
        __syncthreads();
    }

    const float s = 1.0f / 128.0f;
    if (act) {
        #pragma unroll
        for (int j = 0; j < 12; j++) {
            const int de = i0 + 2 * j;
            float a0, a1, a2, a3;
            upk(accE[j][0], a0, a1);
            upk(accE[j][1], a2, a3);
            float4 o;
            o.x = a0 * s; o.y = a1 * s; o.z = a2 * s; o.w = a3 * s;
            *(float4*)(out + (((size_t)b * V_ + de) * H_ + h) * W_ + xb) = o;

            float b0, b1, b2, b3;
            upk(accO[j][0], b0, b1);
            upk(accO[j][1], b2, b3);
            float* oo = out + (((size_t)b * V_ + de + 1) * H_ + h) * W_ + xb;
            oo[1] = b0 * s;
            oo[2] = b1 * s;
            oo[3] = b2 * s;
            if (edge) oo[4] = b3 * s;     // x=xb+4; xg=59 skips x=240
        }
    } else if (xg == 60) {
        // out[x=0, odd d]: never produced by the odd pipeline; 0 since x<d.
        #pragma unroll
        for (int j = 0; j < 12; j++) {
            const int d = i0 + 2 * j + 1;
            out[(((size_t)b * V_ + d) * H_ + h) * W_] = 0.0f;
        }
    }
}

extern "C" void kernel_launch(void* const* d_in, const int* in_sizes, int n_in,
                              void* d_out, int out_size)
{
    const float* L = (const float*)d_in[0];
    const float* R = (const float*)d_in[1];
    float* out = (float*)d_out;

    // +64B tail pad: unguarded lanes (xg 60..63) read up to 15 floats past
    // the last sR row.
    const int smem_bytes = (2 * CC * W_ + 2 * CC * RW) * (int)sizeof(float) + 64;
    cudaFuncSetAttribute(cv_kernel, cudaFuncAttributeMaxDynamicSharedMemorySize,
                         smem_bytes);
    cv_kernel<<<dim3(H_, B_), THREADS, smem_bytes>>>(L, R, out);
}

// round 17
// speedup vs baseline: 1.4739x; 1.0477x over previous
#include <cuda_runtime.h>
#include <cstdint>

// CostVolume: out[b,d,h,x] = (1/128) * sum_c L[b,c,h,x]*R[b,c,h,x-d], x>=d else 0
// B=8 C=128 H=128 W=240 V=48
// R11 platform (XT=4, IT=24, 2-stage operand double-buffering, division-free
// loader) with symmetric parity coverage: odd-d x in [xb, xb+3] =
// scalar + pair + scalar, removing the L[xb+4] smem read, all edge cases,
// and making both parities store aligned float4.
#define B_  8
#define C_  128
#define H_  128
#define W_  240
#define V_  48
#define HW_ (H_*W_)

#define CC   16            // channels per chunk
#define NCH  (C_/CC)       // 8 chunks
#define THREADS 128
#define RW   288           // sR row width: 48 zero pad + 240 data

typedef unsigned long long ull;

__device__ __forceinline__ ull pk(float lo, float hi) {
    ull r; asm("mov.b64 %0, {%1, %2};" : "=l"(r) : "f"(lo), "f"(hi)); return r;
}
__device__ __forceinline__ void upk(ull v, float& lo, float& hi) {
    asm("mov.b64 {%0, %1}, %2;" : "=f"(lo), "=f"(hi) : "l"(v));
}
__device__ __forceinline__ void fma2(ull& acc, ull a, ull b) {
    asm("fma.rn.f32x2 %0, %1, %2, %0;" : "+l"(acc) : "l"(a), "l"(b));
}
__device__ __forceinline__ void cpasync16(uint32_t saddr, const void* g) {
    asm volatile("cp.async.cg.shared.global [%0], [%1], 16;" :: "r"(saddr), "l"(g));
}

struct Stage {
    float4 Lq;
    float  e[28];          // e[k] = R[xb - i0 - 24 + k] (zero-padded)
};

__global__ void __launch_bounds__(THREADS, 3)
cv_kernel(const float* __restrict__ L, const float* __restrict__ R,
          float* __restrict__ out)
{
    extern __shared__ float smem[];
    float* sL = smem;                 // [2][CC][W_]
    float* sR = smem + 2 * CC * W_;   // [2][CC][RW]

    const int tid = threadIdx.x;
    const int h = blockIdx.x;
    const int b = blockIdx.y;

    const int xg = tid & 63;          // 0..63 (60 active)
    const int ig = tid >> 6;          // 0..1
    const int i0 = ig * 24;           // disparity base
    const int xb = xg * 4;
    const bool act = (xg < 60);

    const float* Lbase = L + ((size_t)b * C_ * H_ + h) * W_;
    const float* Rbase = R + ((size_t)b * C_ * H_ + h) * W_;

    // Zero the left pad of sR (x<0 -> 0), both buffers, once.
    for (int idx = tid; idx < 2 * CC * 48; idx += THREADS) {
        int buf = idx / (CC * 48);
        int rem = idx - buf * (CC * 48);
        int r = rem / 48, k = rem - r * 48;
        sR[buf * (CC * RW) + r * RW + k] = 0.0f;
    }

    // --- division-free loader: thread<120 owns (row0, col); rows row0+2k ---
    const bool loader = (tid < 120);
    const int lr0  = (tid >= 60) ? 1 : 0;
    const int lcol = tid - lr0 * 60;             // 0..59 (quad index)
    const float* gL = Lbase + (size_t)lr0 * HW_ + lcol * 4;
    const float* gR = Rbase + (size_t)lr0 * HW_ + lcol * 4;
    const uint32_t sLb = (uint32_t)__cvta_generic_to_shared(sL)
                       + (uint32_t)(lr0 * W_ + lcol * 4) * 4;
    const uint32_t sRb = (uint32_t)__cvta_generic_to_shared(sR)
                       + (uint32_t)(lr0 * RW + 48 + lcol * 4) * 4;

    auto issue_load = [&](int buf) {
        if (loader) {
            const uint32_t dL = sLb + (uint32_t)buf * (CC * W_ * 4);
            const uint32_t dR = sRb + (uint32_t)buf * (CC * RW * 4);
            #pragma unroll
            for (int k = 0; k < 8; k++) {        // rows lr0 + 2k
                cpasync16(dL + k * (2 * W_ * 4), gL + (size_t)k * 2 * HW_);
                cpasync16(dR + k * (2 * RW * 4), gR + (size_t)k * 2 * HW_);
            }
        }
        asm volatile("cp.async.commit_group;");
    };

    // accE[j][0]: d=i0+2j,   x pair (xb,  xb+1)   <- Le0 * P[12-j]
    // accE[j][1]: d=i0+2j,   x pair (xb+2,xb+3)   <- Le1 * P[13-j]
    // accO[j]   : d=i0+2j+1, x pair (xb+1,xb+2)   <- Lo0 * P[12-j]
    // accOs0[j] : d=i0+2j+1, x = xb               <- Lq.x * e[23-2j]
    // accOs3[j] : d=i0+2j+1, x = xb+3             <- Lq.w * e[26-2j]
    ull  accE[12][2], accO[12];
    float accOs0[12], accOs3[12];
    #pragma unroll
    for (int j = 0; j < 12; j++) {
        accE[j][0] = 0ull; accE[j][1] = 0ull; accO[j] = 0ull;
        accOs0[j] = 0.0f;  accOs3[j] = 0.0f;
    }

    issue_load(0);
    gL += CC * HW_; gR += CC * HW_;

    #pragma unroll 1
    for (int ch = 0; ch < NCH; ch++) {
        const int buf = ch & 1;
        if (ch + 1 < NCH) {
            issue_load((ch + 1) & 1);
            gL += CC * HW_; gR += CC * HW_;
            asm volatile("cp.async.wait_group 1;");
        } else {
            asm volatile("cp.async.wait_group 0;");
        }
        __syncthreads();

        if (act) {
            const float* lw = &sL[buf * (CC * W_)] + xb;
            const float* rw = &sR[buf * (CC * RW)] + (xb - i0 + 24);
            Stage SA, SB;

            #define LDS_STAGE(S, cc) do {                                   \
                (S).Lq = *(const float4*)(lw + (cc) * W_);                  \
                _Pragma("unroll")                                           \
                for (int m = 0; m < 7; m++) {                               \
                    float4 v = *(const float4*)(rw + (cc) * RW + 4 * m);    \
                    (S).e[4*m+0] = v.x; (S).e[4*m+1] = v.y;                 \
                    (S).e[4*m+2] = v.z; (S).e[4*m+3] = v.w;                 \
                }                                                           \
            } while (0)

            #define FMA_STAGE(S) do {                                       \
                ull Le0 = pk((S).Lq.x, (S).Lq.y);   /* aligned: elided */   \
                ull Le1 = pk((S).Lq.z, (S).Lq.w);                           \
                ull Lo0 = pk((S).Lq.y, (S).Lq.z);   /* 2 MOVs */            \
                ull P[14];                          /* aligned quad halves */\
                _Pragma("unroll")                                           \
                for (int i = 1; i <= 13; i++)                               \
                    P[i] = pk((S).e[2*i], (S).e[2*i+1]);                    \
                _Pragma("unroll")                                           \
                for (int j = 0; j < 12; j++) {                              \
                    fma2(accE[j][0], Le0, P[12 - j]);                       \
                    fma2(accO[j],    Lo0, P[12 - j]);                       \
                    fma2(accE[j][1], Le1, P[13 - j]);                       \
                    accOs0[j] = fmaf((S).Lq.x, (S).e[23 - 2*j], accOs0[j]); \
                    accOs3[j] = fmaf((S).Lq.w, (S).e[26 - 2*j], accOs3[j]); \
                }                                                           \
            } while (0)

            LDS_STAGE(SA, 0);
            #pragma unroll
            for (int cc = 0; cc < CC; cc += 2) {
                if (cc + 1 < CC) LDS_STAGE(SB, cc + 1);
                FMA_STAGE(SA);
                if (cc + 2 < CC) LDS_STAGE(SA, cc + 2);
                if (cc + 1 < CC) FMA_STAGE(SB);
            }
            #undef LDS_STAGE
            #undef FMA_STAGE
        }
        __syncthreads();
    }

    const float s = 1.0f / 128.0f;
    if (act) {
        #pragma unroll
        for (int j = 0; j < 12; j++) {
            const int de = i0 + 2 * j;
            float a0, a1, a2, a3;
            upk(accE[j][0], a0, a1);
            upk(accE[j][1], a2, a3);
            float4 o;
            o.x = a0 * s; o.y = a1 * s; o.z = a2 * s; o.w = a3 * s;
            *(float4*)(out + (((size_t)b * V_ + de) * H_ + h) * W_ + xb) = o;

            float m1, m2;
            upk(accO[j], m1, m2);
            float4 q;
            q.x = accOs0[j] * s;   // x = xb   (x<d cases auto-zero via pad)
            q.y = m1 * s;          // x = xb+1
            q.z = m2 * s;          // x = xb+2
            q.w = accOs3[j] * s;   // x = xb+3
            *(float4*)(out + (((size_t)b * V_ + de + 1) * H_ + h) * W_ + xb) = q;
        }
    }
}

extern "C" void kernel_launch(void* const* d_in, const int* in_sizes, int n_in,
                              void* d_out, int out_size)
{
    const float* L = (const float*)d_in[0];
    const float* R = (const float*)d_in[1];
    float* out = (float*)d_out;

    const int smem_bytes = (2 * CC * W_ + 2 * CC * RW) * (int)sizeof(float); // 67584
    cudaFuncSetAttribute(cv_kernel, cudaFuncAttributeMaxDynamicSharedMemorySize,
                         smem_bytes);
    cv_kernel<<<dim3(H_, B_), THREADS, smem_bytes>>>(L, R, out);
}